// round 15
// baseline (speedup 1.0000x reference)
#include <cuda_runtime.h>
#include <cuda_bf16.h>
#include <cuda_fp16.h>
#include <math.h>
#include <stdint.h>

#define NN      50000
#define EE      800000
#define IN_DIMV 128
#define EMB_DIMV 64
#define CIN1    192
#define HIDV    128
#define OUT_DIMV 64
#define NGRAPH  128

// ---------------- device scratch (static, no allocation) ----------------
__device__ __align__(128) __nv_bfloat16 g_h0s[(size_t)NN * 2 * CIN1]; // [hi 192][lo 192]
__device__ __align__(128) __nv_bfloat16 g_hs[(size_t)NN * 2 * HIDV];  // [hi 128][lo 128]
__device__ __align__(128) __half g_ht[(size_t)NN * HIDV];             // GEMM out (fp16)
__device__ __align__(128) float g_hA[(size_t)NN * HIDV];              // final layer out
__device__ __align__(128) __nv_bfloat16 g_Wh[3][CIN1 * HIDV];
__device__ __align__(128) __nv_bfloat16 g_Wl[3][CIN1 * HIDV];
__device__ float g_as[NN];
__device__ float g_ad[NN];
__device__ unsigned g_asmax[3];
__device__ int   g_deg[NN];
__device__ int   g_cur[NN];
__device__ int   g_rowptr[NN];
__device__ int   g_col[EE];
__device__ int   g_sval[64];
__device__ int   g_sflag[64];
__device__ float g_pool[NGRAPH * HIDV];

__device__ __forceinline__ float gelu_tanh(float v) {
    float c = 0.7978845608028654f * (v + 0.044715f * v * v * v);
    return 0.5f * v * (1.0f + tanhf(c));
}
__device__ __forceinline__ float lrelu02(float v) { return v > 0.f ? v : 0.2f * v; }
__device__ __forceinline__ uint32_t smem_u32(const void* p) {
    uint32_t a;
    asm("{ .reg .u64 t; cvta.to.shared.u64 t, %1; cvt.u32.u64 %0, t; }" : "=r"(a) : "l"(p));
    return a;
}
__device__ __forceinline__ unsigned encf(float f) {
    unsigned u = __float_as_uint(f);
    return (u & 0x80000000u) ? ~u : (u | 0x80000000u);
}
__device__ __forceinline__ float decf(unsigned u) {
    u = (u & 0x80000000u) ? (u & 0x7fffffffu) : ~u;
    return __uint_as_float(u);
}

// ---------------- init: zero counters + split weights ----------------
__global__ void k_init(const float* __restrict__ W1, const float* __restrict__ W2,
                       const float* __restrict__ W3) {
    const int NW1 = CIN1 * HIDV, NW2 = HIDV * HIDV;
    for (int i = blockIdx.x * blockDim.x + threadIdx.x;
         i < NN + NGRAPH * HIDV + 128 + 4 + NW1 + 2 * NW2;
         i += gridDim.x * blockDim.x) {
        int q = i;
        if (q < NN) { g_deg[q] = 0; g_cur[q] = 0; continue; }
        q -= NN;
        if (q < NGRAPH * HIDV) { g_pool[q] = 0.f; continue; }
        q -= NGRAPH * HIDV;
        if (q < 128) { if (q < 64) g_sval[q] = 0; else g_sflag[q - 64] = 0; continue; }
        q -= 128;
        if (q < 4) { if (q < 3) g_asmax[q] = 0u; continue; }
        q -= 4;
        const float* W; int l, idx;
        if (q < NW1)            { W = W1; l = 0; idx = q; }
        else if (q < NW1 + NW2) { W = W2; l = 1; idx = q - NW1; }
        else                    { W = W3; l = 2; idx = q - NW1 - NW2; }
        float v = W[idx];
        __nv_bfloat16 h = __float2bfloat16_rn(v);
        g_Wh[l][idx] = h;
        g_Wl[l][idx] = __float2bfloat16_rn(v - __bfloat162float(h));
    }
}

// ---------------- h0 split + histogram ----------------
__global__ void k_h0(const float* __restrict__ x, const int* __restrict__ nodeidx,
                     const float* __restrict__ emb, const int* __restrict__ dst) {
    int n = blockIdx.x;
    int c = threadIdx.x;
    float v = x[(size_t)n * IN_DIMV + c];
    float sq = v * v;
    #pragma unroll
    for (int o = 16; o > 0; o >>= 1) sq += __shfl_xor_sync(0xffffffffu, sq, o);
    __shared__ float red[4];
    if ((c & 31) == 0) red[c >> 5] = sq;
    __syncthreads();
    float nrm = sqrtf(red[0] + red[1] + red[2] + red[3]);
    if (nrm == 0.0f) nrm = 1e-8f;
    float xv = v / nrm;
    __nv_bfloat16* row = g_h0s + (size_t)n * (2 * CIN1);
    __nv_bfloat16 h = __float2bfloat16_rn(xv);
    row[c] = h;
    row[CIN1 + c] = __float2bfloat16_rn(xv - __bfloat162float(h));
    if (c < EMB_DIMV) {
        float ev = emb[(size_t)nodeidx[n] * EMB_DIMV + c];
        __nv_bfloat16 eh = __float2bfloat16_rn(ev);
        row[IN_DIMV + c] = eh;
        row[CIN1 + IN_DIMV + c] = __float2bfloat16_rn(ev - __bfloat162float(eh));
    }
    int e = blockIdx.x * blockDim.x + threadIdx.x;
    if (e < EE) atomicAdd(&g_deg[dst[e]], 1);
}

// ---------------- chained single-kernel exclusive scan ----------------
__global__ void k_scan() {
    int tid = threadIdx.x, bid = blockIdx.x;
    int i = bid * 1024 + tid;
    int v = (i < NN) ? g_deg[i] : 0;
    int lane = tid & 31, wid = tid >> 5;
    int xv = v;
    #pragma unroll
    for (int o = 1; o < 32; o <<= 1) {
        int t = __shfl_up_sync(0xffffffffu, xv, o);
        if (lane >= o) xv += t;
    }
    __shared__ int ws[32];
    if (lane == 31) ws[wid] = xv;
    __syncthreads();
    if (wid == 0) {
        int y = ws[lane];
        #pragma unroll
        for (int o = 1; o < 32; o <<= 1) {
            int t = __shfl_up_sync(0xffffffffu, y, o);
            if (lane >= o) y += t;
        }
        ws[lane] = y;
    }
    __syncthreads();
    int incl = xv + (wid ? ws[wid - 1] : 0);
    int total = ws[31];
    __shared__ int sbase;
    if (tid == 0) {
        int base = 0;
        if (bid > 0) {
            while (((volatile int*)g_sflag)[bid] == 0) {}
            __threadfence();
            base = g_sval[bid];
        }
        g_sval[bid + 1] = base + total;
        __threadfence();
        ((volatile int*)g_sflag)[bid + 1] = 1;
        sbase = base;
    }
    __syncthreads();
    if (i < NN) g_rowptr[i] = incl - v + sbase;
}

__global__ void k_scatter(const int* __restrict__ src, const int* __restrict__ dst) {
    for (int e = blockIdx.x * blockDim.x + threadIdx.x; e < EE; e += gridDim.x * blockDim.x) {
        int d = dst[e];
        int p = g_rowptr[d] + atomicAdd(&g_cur[d], 1);
        g_col[p] = src[e];
    }
}

// ---------------- GEMM: 256 thr, 128-row tile, K-chunked, x4 B-ldmatrix ----
__global__ __launch_bounds__(256, 2) void k_mma(int insel, int K, int KC, int widx,
        const float* __restrict__ a_s, const float* __restrict__ a_d) {
    extern __shared__ char smem[];
    const int APAD = KC + 8;
    const int BPAD = 136;
    __nv_bfloat16* A1 = (__nv_bfloat16*)smem;
    __nv_bfloat16* A2 = A1 + 128 * APAD;
    __nv_bfloat16* B1 = A2 + 128 * APAD;
    __nv_bfloat16* B2 = B1 + KC * BPAD;
    float* s_as = (float*)(B2 + KC * BPAD);
    float* s_ad = s_as + 128;

    int tid = threadIdx.x, wid = tid >> 5, lane = tid & 31;
    int row0 = blockIdx.x * 128;
    const __nv_bfloat16* Ain = insel == 0 ? g_h0s : g_hs;
    const __nv_bfloat16* Wh = g_Wh[widx];
    const __nv_bfloat16* Wl = g_Wl[widx];

    if (tid < 128) { s_as[tid] = a_s[tid]; s_ad[tid] = a_d[tid]; }

    float acc[16][4];
    #pragma unroll
    for (int n = 0; n < 16; n++)
        #pragma unroll
        for (int i = 0; i < 4; i++) acc[n][i] = 0.f;

    int rw = wid * 16;
    const int KC8 = KC >> 3;
    const int chunksA = 128 * KC8;
    const int chunksB = KC * 16;

    for (int c0 = 0; c0 < K; c0 += KC) {
        // load A chunk (pre-split rows: [hi K][lo K], cols c0..c0+KC)
        for (int q = tid; q < 2 * chunksA; q += 256) {
            int hi = q < chunksA;
            int qq = hi ? q : q - chunksA;
            int r = qq / KC8, c = qq - r * KC8;
            uint4 val = make_uint4(0, 0, 0, 0);
            int gr = row0 + r;
            if (gr < NN) val = *(const uint4*)(Ain + (size_t)gr * (2 * K) + (hi ? 0 : K) + c0 + c * 8);
            *(uint4*)((hi ? A1 : A2) + r * APAD + c * 8) = val;
        }
        // load B chunk (pre-split weights, rows c0..c0+KC)
        for (int q = tid; q < 2 * chunksB; q += 256) {
            int hi = q < chunksB;
            int qq = hi ? q : q - chunksB;
            int k = qq >> 4, c = qq & 15;
            uint4 val = *(const uint4*)((hi ? Wh : Wl) + (size_t)(c0 + k) * 128 + c * 8);
            *(uint4*)((hi ? B1 : B2) + k * BPAD + c * 8) = val;
        }
        __syncthreads();

        uint32_t a1base = smem_u32(A1 + (rw + (lane & 15)) * APAD + ((lane >> 4) << 3));
        uint32_t a2base = smem_u32(A2 + (rw + (lane & 15)) * APAD + ((lane >> 4) << 3));
        // x4-trans B base: lanes 0-15 -> cols +0..7, lanes 16-31 -> cols +8..15
        uint32_t b1base = smem_u32(B1 + (lane & 15) * BPAD + ((lane >> 4) << 3));
        uint32_t b2base = smem_u32(B2 + (lane & 15) * BPAD + ((lane >> 4) << 3));

        // sweep 1: (A1 + A2) @ B1 -- one x4 B load feeds 4 HMMAs
        #pragma unroll 1
        for (int k0 = 0; k0 < KC; k0 += 16) {
            uint32_t p0, p1, p2, p3, q0, q1, q2, q3;
            asm volatile("ldmatrix.sync.aligned.m8n8.x4.shared.b16 {%0,%1,%2,%3}, [%4];"
                         : "=r"(p0), "=r"(p1), "=r"(p2), "=r"(p3) : "r"(a1base + (uint32_t)k0 * 2));
            asm volatile("ldmatrix.sync.aligned.m8n8.x4.shared.b16 {%0,%1,%2,%3}, [%4];"
                         : "=r"(q0), "=r"(q1), "=r"(q2), "=r"(q3) : "r"(a2base + (uint32_t)k0 * 2));
            uint32_t brow = b1base + (uint32_t)(k0 * BPAD) * 2;
            #pragma unroll
            for (int n2 = 0; n2 < 8; n2++) {
                uint32_t b0, b1, b2, b3;
                asm volatile("ldmatrix.sync.aligned.m8n8.x4.trans.shared.b16 {%0,%1,%2,%3}, [%4];"
                             : "=r"(b0), "=r"(b1), "=r"(b2), "=r"(b3)
                             : "r"(brow + (uint32_t)(n2 * 16) * 2));
                asm volatile("mma.sync.aligned.m16n8k16.row.col.f32.bf16.bf16.f32 "
                             "{%0,%1,%2,%3}, {%4,%5,%6,%7}, {%8,%9}, {%0,%1,%2,%3};"
                             : "+f"(acc[2*n2][0]), "+f"(acc[2*n2][1]), "+f"(acc[2*n2][2]), "+f"(acc[2*n2][3])
                             : "r"(p0), "r"(p1), "r"(p2), "r"(p3), "r"(b0), "r"(b1));
                asm volatile("mma.sync.aligned.m16n8k16.row.col.f32.bf16.bf16.f32 "
                             "{%0,%1,%2,%3}, {%4,%5,%6,%7}, {%8,%9}, {%0,%1,%2,%3};"
                             : "+f"(acc[2*n2+1][0]), "+f"(acc[2*n2+1][1]), "+f"(acc[2*n2+1][2]), "+f"(acc[2*n2+1][3])
                             : "r"(p0), "r"(p1), "r"(p2), "r"(p3), "r"(b2), "r"(b3));
                asm volatile("mma.sync.aligned.m16n8k16.row.col.f32.bf16.bf16.f32 "
                             "{%0,%1,%2,%3}, {%4,%5,%6,%7}, {%8,%9}, {%0,%1,%2,%3};"
                             : "+f"(acc[2*n2][0]), "+f"(acc[2*n2][1]), "+f"(acc[2*n2][2]), "+f"(acc[2*n2][3])
                             : "r"(q0), "r"(q1), "r"(q2), "r"(q3), "r"(b0), "r"(b1));
                asm volatile("mma.sync.aligned.m16n8k16.row.col.f32.bf16.bf16.f32 "
                             "{%0,%1,%2,%3}, {%4,%5,%6,%7}, {%8,%9}, {%0,%1,%2,%3};"
                             : "+f"(acc[2*n2+1][0]), "+f"(acc[2*n2+1][1]), "+f"(acc[2*n2+1][2]), "+f"(acc[2*n2+1][3])
                             : "r"(q0), "r"(q1), "r"(q2), "r"(q3), "r"(b2), "r"(b3));
            }
        }
        // sweep 2: A1 @ B2
        #pragma unroll 1
        for (int k0 = 0; k0 < KC; k0 += 16) {
            uint32_t p0, p1, p2, p3;
            asm volatile("ldmatrix.sync.aligned.m8n8.x4.shared.b16 {%0,%1,%2,%3}, [%4];"
                         : "=r"(p0), "=r"(p1), "=r"(p2), "=r"(p3) : "r"(a1base + (uint32_t)k0 * 2));
            uint32_t brow = b2base + (uint32_t)(k0 * BPAD) * 2;
            #pragma unroll
            for (int n2 = 0; n2 < 8; n2++) {
                uint32_t b0, b1, b2, b3;
                asm volatile("ldmatrix.sync.aligned.m8n8.x4.trans.shared.b16 {%0,%1,%2,%3}, [%4];"
                             : "=r"(b0), "=r"(b1), "=r"(b2), "=r"(b3)
                             : "r"(brow + (uint32_t)(n2 * 16) * 2));
                asm volatile("mma.sync.aligned.m16n8k16.row.col.f32.bf16.bf16.f32 "
                             "{%0,%1,%2,%3}, {%4,%5,%6,%7}, {%8,%9}, {%0,%1,%2,%3};"
                             : "+f"(acc[2*n2][0]), "+f"(acc[2*n2][1]), "+f"(acc[2*n2][2]), "+f"(acc[2*n2][3])
                             : "r"(p0), "r"(p1), "r"(p2), "r"(p3), "r"(b0), "r"(b1));
                asm volatile("mma.sync.aligned.m16n8k16.row.col.f32.bf16.bf16.f32 "
                             "{%0,%1,%2,%3}, {%4,%5,%6,%7}, {%8,%9}, {%0,%1,%2,%3};"
                             : "+f"(acc[2*n2+1][0]), "+f"(acc[2*n2+1][1]), "+f"(acc[2*n2+1][2]), "+f"(acc[2*n2+1][3])
                             : "r"(p0), "r"(p1), "r"(p2), "r"(p3), "r"(b2), "r"(b3));
            }
        }
        __syncthreads();
    }

    // epilogue: fp16 g_ht + fused a_s/a_d dots + global as max
    int qrow = lane >> 2;
    int qcol = (lane & 3) * 2;
    int r0 = rw + qrow, r1 = r0 + 8;
    int gr0 = row0 + r0, gr1 = row0 + r1;
    float as0 = 0.f, ad0 = 0.f, as1 = 0.f, ad1 = 0.f;
    #pragma unroll
    for (int n = 0; n < 16; n++) {
        int c = n * 8 + qcol;
        float w0 = s_as[c], w1 = s_as[c + 1];
        float u0 = s_ad[c], u1 = s_ad[c + 1];
        as0 += acc[n][0] * w0 + acc[n][1] * w1;
        ad0 += acc[n][0] * u0 + acc[n][1] * u1;
        as1 += acc[n][2] * w0 + acc[n][3] * w1;
        ad1 += acc[n][2] * u0 + acc[n][3] * u1;
    }
    if (gr0 < NN) {
        __half* d0 = g_ht + (size_t)gr0 * HIDV;
        #pragma unroll
        for (int n = 0; n < 16; n++)
            *(__half2*)(d0 + n * 8 + qcol) = __floats2half2_rn(acc[n][0], acc[n][1]);
    }
    if (gr1 < NN) {
        __half* d1 = g_ht + (size_t)gr1 * HIDV;
        #pragma unroll
        for (int n = 0; n < 16; n++)
            *(__half2*)(d1 + n * 8 + qcol) = __floats2half2_rn(acc[n][2], acc[n][3]);
    }
    #pragma unroll
    for (int o = 1; o < 4; o <<= 1) {
        as0 += __shfl_xor_sync(0xffffffffu, as0, o);
        ad0 += __shfl_xor_sync(0xffffffffu, ad0, o);
        as1 += __shfl_xor_sync(0xffffffffu, as1, o);
        ad1 += __shfl_xor_sync(0xffffffffu, ad1, o);
    }
    float mv = -3.4e38f;
    if ((lane & 3) == 0) {
        if (gr0 < NN) { g_as[gr0] = as0; g_ad[gr0] = ad0; mv = fmaxf(mv, as0); }
        if (gr1 < NN) { g_as[gr1] = as1; g_ad[gr1] = ad1; mv = fmaxf(mv, as1); }
    }
    #pragma unroll
    for (int o = 16; o > 0; o >>= 1) mv = fmaxf(mv, __shfl_xor_sync(0xffffffffu, mv, o));
    if (lane == 0 && mv > -3.0e38f) atomicMax(&g_asmax[widx], encf(mv));
}

// ---------------- aggregation: single-pass softmax, fp16 gather, MLP 8 ----
__global__ __launch_bounds__(256) void k_agg(const float* __restrict__ bias,
                                             int layer, int mode) {
    __shared__ uint2 pairs[8][32];
    int w = (blockIdx.x * blockDim.x + threadIdx.x) >> 5;
    if (w >= NN) return;
    int lane = threadIdx.x & 31;
    int wl = (threadIdx.x >> 5) & 7;

    float ad = g_ad[w];
    float m = lrelu02(decf(g_asmax[layer]) + ad);
    float wself = __expf(lrelu02(g_as[w] + ad) - m);
    uint2 hv0 = *(const uint2*)(g_ht + (size_t)w * HIDV + lane * 4);
    float2 hl = __half22float2(*(__half2*)&hv0.x);
    float2 hh = __half22float2(*(__half2*)&hv0.y);
    float4 acc = make_float4(wself * hl.x, wself * hl.y, wself * hh.x, wself * hh.y);
    float se = 0.f;

    int beg = g_rowptr[w], cnt = g_deg[w];
    for (int base = 0; base < cnt; base += 32) {
        int i = base + lane;
        int srci = 0;
        float wgt = 0.f;
        if (i < cnt) {
            srci = g_col[beg + i];
            wgt = __expf(lrelu02(g_as[srci] + ad) - m);
            se += wgt;
        }
        __syncwarp();
        pairs[wl][lane] = make_uint2((unsigned)srci, __float_as_uint(wgt));
        __syncwarp();
        int lim = min(32, cnt - base);
        int j = 0;
        for (; j + 8 <= lim; j += 8) {
            uint2 p0 = pairs[wl][j],     p1 = pairs[wl][j + 1];
            uint2 p2 = pairs[wl][j + 2], p3 = pairs[wl][j + 3];
            uint2 p4 = pairs[wl][j + 4], p5 = pairs[wl][j + 5];
            uint2 p6 = pairs[wl][j + 6], p7 = pairs[wl][j + 7];
            uint2 r0 = *(const uint2*)(g_ht + (size_t)p0.x * HIDV + lane * 4);
            uint2 r1 = *(const uint2*)(g_ht + (size_t)p1.x * HIDV + lane * 4);
            uint2 r2 = *(const uint2*)(g_ht + (size_t)p2.x * HIDV + lane * 4);
            uint2 r3 = *(const uint2*)(g_ht + (size_t)p3.x * HIDV + lane * 4);
            uint2 r4 = *(const uint2*)(g_ht + (size_t)p4.x * HIDV + lane * 4);
            uint2 r5 = *(const uint2*)(g_ht + (size_t)p5.x * HIDV + lane * 4);
            uint2 r6 = *(const uint2*)(g_ht + (size_t)p6.x * HIDV + lane * 4);
            uint2 r7 = *(const uint2*)(g_ht + (size_t)p7.x * HIDV + lane * 4);
            float w0 = __uint_as_float(p0.y), w1 = __uint_as_float(p1.y);
            float w2 = __uint_as_float(p2.y), w3 = __uint_as_float(p3.y);
            float w4 = __uint_as_float(p4.y), w5 = __uint_as_float(p5.y);
            float w6 = __uint_as_float(p6.y), w7 = __uint_as_float(p7.y);
            float2 a0 = __half22float2(*(__half2*)&r0.x), b0 = __half22float2(*(__half2*)&r0.y);
            float2 a1 = __half22float2(*(__half2*)&r1.x), b1 = __half22float2(*(__half2*)&r1.y);
            float2 a2 = __half22float2(*(__half2*)&r2.x), b2 = __half22float2(*(__half2*)&r2.y);
            float2 a3 = __half22float2(*(__half2*)&r3.x), b3 = __half22float2(*(__half2*)&r3.y);
            float2 a4 = __half22float2(*(__half2*)&r4.x), b4 = __half22float2(*(__half2*)&r4.y);
            float2 a5 = __half22float2(*(__half2*)&r5.x), b5 = __half22float2(*(__half2*)&r5.y);
            float2 a6 = __half22float2(*(__half2*)&r6.x), b6 = __half22float2(*(__half2*)&r6.y);
            float2 a7 = __half22float2(*(__half2*)&r7.x), b7 = __half22float2(*(__half2*)&r7.y);
            acc.x += w0 * a0.x + w1 * a1.x + w2 * a2.x + w3 * a3.x
                   + w4 * a4.x + w5 * a5.x + w6 * a6.x + w7 * a7.x;
            acc.y += w0 * a0.y + w1 * a1.y + w2 * a2.y + w3 * a3.y
                   + w4 * a4.y + w5 * a5.y + w6 * a6.y + w7 * a7.y;
            acc.z += w0 * b0.x + w1 * b1.x + w2 * b2.x + w3 * b3.x
                   + w4 * b4.x + w5 * b5.x + w6 * b6.x + w7 * b7.x;
            acc.w += w0 * b0.y + w1 * b1.y + w2 * b2.y + w3 * b3.y
                   + w4 * b4.y + w5 * b5.y + w6 * b6.y + w7 * b7.y;
        }
        for (; j < lim; j++) {
            uint2 p = pairs[wl][j];
            float wj = __uint_as_float(p.y);
            uint2 rv = *(const uint2*)(g_ht + (size_t)p.x * HIDV + lane * 4);
            float2 aa = __half22float2(*(__half2*)&rv.x), bb2 = __half22float2(*(__half2*)&rv.y);
            acc.x += wj * aa.x; acc.y += wj * aa.y;
            acc.z += wj * bb2.x; acc.w += wj * bb2.y;
        }
    }
    #pragma unroll
    for (int o = 16; o > 0; o >>= 1) se += __shfl_xor_sync(0xffffffffu, se, o);
    float inv = 1.0f / (wself + se);
    float4 bb = *(const float4*)(bias + lane * 4);
    float4 o;
    o.x = gelu_tanh(acc.x * inv + bb.x);
    o.y = gelu_tanh(acc.y * inv + bb.y);
    o.z = gelu_tanh(acc.z * inv + bb.z);
    o.w = gelu_tanh(acc.w * inv + bb.w);
    if (mode == 0) {
        __nv_bfloat16 h0 = __float2bfloat16_rn(o.x), h1 = __float2bfloat16_rn(o.y);
        __nv_bfloat16 h2 = __float2bfloat16_rn(o.z), h3 = __float2bfloat16_rn(o.w);
        __nv_bfloat16 l0 = __float2bfloat16_rn(o.x - __bfloat162float(h0));
        __nv_bfloat16 l1 = __float2bfloat16_rn(o.y - __bfloat162float(h1));
        __nv_bfloat16 l2 = __float2bfloat16_rn(o.z - __bfloat162float(h2));
        __nv_bfloat16 l3 = __float2bfloat16_rn(o.w - __bfloat162float(h3));
        __nv_bfloat16* row = g_hs + (size_t)w * (2 * HIDV);
        uint2 hv = make_uint2((uint32_t)__bfloat16_as_ushort(h0) | ((uint32_t)__bfloat16_as_ushort(h1) << 16),
                              (uint32_t)__bfloat16_as_ushort(h2) | ((uint32_t)__bfloat16_as_ushort(h3) << 16));
        uint2 lv = make_uint2((uint32_t)__bfloat16_as_ushort(l0) | ((uint32_t)__bfloat16_as_ushort(l1) << 16),
                              (uint32_t)__bfloat16_as_ushort(l2) | ((uint32_t)__bfloat16_as_ushort(l3) << 16));
        *(uint2*)(row + lane * 4) = hv;
        *(uint2*)(row + HIDV + lane * 4) = lv;
    } else {
        *(float4*)(g_hA + (size_t)w * HIDV + lane * 4) = o;
    }
}

// ---------------- global add pool: 1024 blocks ----------------
__global__ void k_pool(const int* __restrict__ batch) {
    const float* h = g_hA;
    int c = threadIdx.x;
    int per = (NN + gridDim.x - 1) / gridDim.x;
    int n0 = blockIdx.x * per;
    int n1 = n0 + per;
    if (n1 > NN) n1 = NN;
    if (n0 >= n1) return;
    float acc = 0.f;
    int cg = batch[n0];
    #pragma unroll 4
    for (int n = n0; n < n1; n++) {
        int bg = batch[n];
        if (bg != cg) {
            atomicAdd(&g_pool[(size_t)cg * HIDV + c], acc);
            acc = 0.f;
            cg = bg;
        }
        acc += h[(size_t)n * HIDV + c];
    }
    atomicAdd(&g_pool[(size_t)cg * HIDV + c], acc);
}

// ---------------- final FC + leaky ----------------
__global__ void k_fc(const float* __restrict__ fcW, const float* __restrict__ fcb,
                     float* __restrict__ out) {
    int gi = blockIdx.x;
    int oc = threadIdx.x;
    float s = fcb[oc];
    #pragma unroll 8
    for (int k = 0; k < HIDV; k++)
        s += g_pool[(size_t)gi * HIDV + k] * fcW[(size_t)k * OUT_DIMV + oc];
    s = s > 0.f ? s : 0.01f * s;
    out[(size_t)gi * OUT_DIMV + oc] = s;
}

// ---------------- launcher ----------------
extern "C" void kernel_launch(void* const* d_in, const int* in_sizes, int n_in,
                              void* d_out, int out_size) {
    const float* x       = (const float*)d_in[0];
    const int*   nodeidx = (const int*)  d_in[1];
    const int*   eidx    = (const int*)  d_in[2];
    const int*   batch   = (const int*)  d_in[3];
    const float* emb     = (const float*)d_in[4];
    const float* W1      = (const float*)d_in[5];
    const float* a1s     = (const float*)d_in[6];
    const float* a1d     = (const float*)d_in[7];
    const float* b1      = (const float*)d_in[8];
    const float* W2      = (const float*)d_in[9];
    const float* a2s     = (const float*)d_in[10];
    const float* a2d     = (const float*)d_in[11];
    const float* b2      = (const float*)d_in[12];
    const float* W3      = (const float*)d_in[13];
    const float* a3s     = (const float*)d_in[14];
    const float* a3d     = (const float*)d_in[15];
    const float* b3      = (const float*)d_in[16];
    const float* fcW     = (const float*)d_in[17];
    const float* fcb     = (const float*)d_in[18];
    float* out = (float*)d_out;

    const int* src = eidx;
    const int* dst = eidx + EE;

    // KC=96 for K=192 (2 chunks, ~106 KB), KC=64 for K=128 (2 chunks, ~73 KB)
    const int smem1 = (2 * 128 * (96 + 8) + 2 * 96 * 136) * 2 + 1024;
    const int smem2 = (2 * 128 * (64 + 8) + 2 * 64 * 136) * 2 + 1024;
    cudaFuncSetAttribute(k_mma, cudaFuncAttributeMaxDynamicSharedMemorySize,
                         smem1 > smem2 ? smem1 : smem2);

    const int mma_blocks = (NN + 127) / 128;
    const int agg_blocks = (NN * 32 + 255) / 256;

    k_init<<<242, 512>>>(W1, W2, W3);                                  // 0
    k_h0<<<NN, 128>>>(x, nodeidx, emb, dst);                           // 1 (+hist)
    k_scan<<<49, 1024>>>();                                            // 2
    k_mma<<<mma_blocks, 256, smem1>>>(0, CIN1, 96, 0, a1s, a1d);       // 3  <- ncu slot
    k_scatter<<<1600, 512>>>(src, dst);                                // 4
    k_agg<<<agg_blocks, 256>>>(b1, 0, 0);                              // 5
    k_mma<<<mma_blocks, 256, smem2>>>(1, HIDV, 64, 1, a2s, a2d);       // 6
    k_agg<<<agg_blocks, 256>>>(b2, 1, 0);                              // 7
    k_mma<<<mma_blocks, 256, smem2>>>(1, HIDV, 64, 2, a3s, a3d);       // 8
    k_agg<<<agg_blocks, 256>>>(b3, 2, 1);                              // 9
    k_pool<<<1024, HIDV>>>(batch);                                     // 10
    k_fc<<<NGRAPH, OUT_DIMV>>>(fcW, fcb, out);                         // 11
}

// round 17
// speedup vs baseline: 1.0731x; 1.0731x over previous
#include <cuda_runtime.h>
#include <cuda_bf16.h>
#include <cuda_fp16.h>
#include <math.h>
#include <stdint.h>

#define NN      50000
#define EE      800000
#define IN_DIMV 128
#define EMB_DIMV 64
#define CIN1    192
#define HIDV    128
#define OUT_DIMV 64
#define NGRAPH  128

// ---------------- device scratch (static, no allocation) ----------------
__device__ __align__(128) __half g_h0s[(size_t)NN * 2 * CIN1];  // [hi 192][lo 192] fp16
__device__ __align__(128) __half g_hs[(size_t)NN * 2 * HIDV];   // [hi 128][lo 128] fp16
__device__ __align__(128) __half g_ht[(size_t)NN * HIDV];       // GEMM out (fp16)
__device__ __align__(128) float g_hA[(size_t)NN * HIDV];        // final layer out
__device__ __align__(128) __half g_Wh[3][CIN1 * HIDV];          // fp16 weights
__device__ float g_as[NN];
__device__ float g_ad[NN];
__device__ unsigned g_asmax[3];
__device__ int   g_deg[NN];
__device__ int   g_cur[NN];
__device__ int   g_rowptr[NN];
__device__ int   g_col[EE];
__device__ int   g_sval[64];
__device__ int   g_sflag[64];
__device__ float g_pool[NGRAPH * HIDV];

__device__ __forceinline__ float gelu_tanh(float v) {
    float c = 0.7978845608028654f * (v + 0.044715f * v * v * v);
    return 0.5f * v * (1.0f + tanhf(c));
}
__device__ __forceinline__ float lrelu02(float v) { return v > 0.f ? v : 0.2f * v; }
__device__ __forceinline__ uint32_t smem_u32(const void* p) {
    uint32_t a;
    asm("{ .reg .u64 t; cvta.to.shared.u64 t, %1; cvt.u32.u64 %0, t; }" : "=r"(a) : "l"(p));
    return a;
}
__device__ __forceinline__ unsigned encf(float f) {
    unsigned u = __float_as_uint(f);
    return (u & 0x80000000u) ? ~u : (u | 0x80000000u);
}
__device__ __forceinline__ float decf(unsigned u) {
    u = (u & 0x80000000u) ? (u & 0x7fffffffu) : ~u;
    return __uint_as_float(u);
}

// ---------------- init: zero counters + fp16 weights ----------------
__global__ void k_init(const float* __restrict__ W1, const float* __restrict__ W2,
                       const float* __restrict__ W3) {
    const int NW1 = CIN1 * HIDV, NW2 = HIDV * HIDV;
    for (int i = blockIdx.x * blockDim.x + threadIdx.x;
         i < NN + NGRAPH * HIDV + 128 + 4 + NW1 + 2 * NW2;
         i += gridDim.x * blockDim.x) {
        int q = i;
        if (q < NN) { g_deg[q] = 0; g_cur[q] = 0; continue; }
        q -= NN;
        if (q < NGRAPH * HIDV) { g_pool[q] = 0.f; continue; }
        q -= NGRAPH * HIDV;
        if (q < 128) { if (q < 64) g_sval[q] = 0; else g_sflag[q - 64] = 0; continue; }
        q -= 128;
        if (q < 4) { if (q < 3) g_asmax[q] = 0u; continue; }
        q -= 4;
        const float* W; int l, idx;
        if (q < NW1)            { W = W1; l = 0; idx = q; }
        else if (q < NW1 + NW2) { W = W2; l = 1; idx = q - NW1; }
        else                    { W = W3; l = 2; idx = q - NW1 - NW2; }
        g_Wh[l][idx] = __float2half_rn(W[idx]);
    }
}

// ---------------- h0 split (fp16 hi/lo) + histogram ----------------
__global__ void k_h0(const float* __restrict__ x, const int* __restrict__ nodeidx,
                     const float* __restrict__ emb, const int* __restrict__ dst) {
    int n = blockIdx.x;
    int c = threadIdx.x;
    float v = x[(size_t)n * IN_DIMV + c];
    float sq = v * v;
    #pragma unroll
    for (int o = 16; o > 0; o >>= 1) sq += __shfl_xor_sync(0xffffffffu, sq, o);
    __shared__ float red[4];
    if ((c & 31) == 0) red[c >> 5] = sq;
    __syncthreads();
    float nrm = sqrtf(red[0] + red[1] + red[2] + red[3]);
    if (nrm == 0.0f) nrm = 1e-8f;
    float xv = v / nrm;
    __half* row = g_h0s + (size_t)n * (2 * CIN1);
    __half h = __float2half_rn(xv);
    row[c] = h;
    row[CIN1 + c] = __float2half_rn(xv - __half2float(h));
    if (c < EMB_DIMV) {
        float ev = emb[(size_t)nodeidx[n] * EMB_DIMV + c];
        __half eh = __float2half_rn(ev);
        row[IN_DIMV + c] = eh;
        row[CIN1 + IN_DIMV + c] = __float2half_rn(ev - __half2float(eh));
    }
    int e = blockIdx.x * blockDim.x + threadIdx.x;
    if (e < EE) atomicAdd(&g_deg[dst[e]], 1);
}

// ---------------- chained single-kernel exclusive scan ----------------
__global__ void k_scan() {
    int tid = threadIdx.x, bid = blockIdx.x;
    int i = bid * 1024 + tid;
    int v = (i < NN) ? g_deg[i] : 0;
    int lane = tid & 31, wid = tid >> 5;
    int xv = v;
    #pragma unroll
    for (int o = 1; o < 32; o <<= 1) {
        int t = __shfl_up_sync(0xffffffffu, xv, o);
        if (lane >= o) xv += t;
    }
    __shared__ int ws[32];
    if (lane == 31) ws[wid] = xv;
    __syncthreads();
    if (wid == 0) {
        int y = ws[lane];
        #pragma unroll
        for (int o = 1; o < 32; o <<= 1) {
            int t = __shfl_up_sync(0xffffffffu, y, o);
            if (lane >= o) y += t;
        }
        ws[lane] = y;
    }
    __syncthreads();
    int incl = xv + (wid ? ws[wid - 1] : 0);
    int total = ws[31];
    __shared__ int sbase;
    if (tid == 0) {
        int base = 0;
        if (bid > 0) {
            while (((volatile int*)g_sflag)[bid] == 0) {}
            __threadfence();
            base = g_sval[bid];
        }
        g_sval[bid + 1] = base + total;
        __threadfence();
        ((volatile int*)g_sflag)[bid + 1] = 1;
        sbase = base;
    }
    __syncthreads();
    if (i < NN) g_rowptr[i] = incl - v + sbase;
}

__global__ void k_scatter(const int* __restrict__ src, const int* __restrict__ dst) {
    for (int e = blockIdx.x * blockDim.x + threadIdx.x; e < EE; e += gridDim.x * blockDim.x) {
        int d = dst[e];
        int p = g_rowptr[d] + atomicAdd(&g_cur[d], 1);
        g_col[p] = src[e];
    }
}

// ---------------- GEMM: fp16 (A1+A2) @ B, 256 thr, 128-row tile, 2 CTAs/SM ----
__global__ __launch_bounds__(256, 2) void k_mma(int insel, int K, int KC, int widx,
        const float* __restrict__ a_s, const float* __restrict__ a_d) {
    extern __shared__ char smem[];
    const int APAD = KC + 8;
    const int BPAD = 136;
    __half* A1 = (__half*)smem;
    __half* A2 = A1 + 128 * APAD;
    __half* B1 = A2 + 128 * APAD;
    float* s_as = (float*)(B1 + KC * BPAD);
    float* s_ad = s_as + 128;

    int tid = threadIdx.x, wid = tid >> 5, lane = tid & 31;
    int row0 = blockIdx.x * 128;
    const __half* Ain = insel == 0 ? g_h0s : g_hs;
    const __half* Wh = g_Wh[widx];

    if (tid < 128) { s_as[tid] = a_s[tid]; s_ad[tid] = a_d[tid]; }

    float acc[16][4];
    #pragma unroll
    for (int n = 0; n < 16; n++)
        #pragma unroll
        for (int i = 0; i < 4; i++) acc[n][i] = 0.f;

    int rw = wid * 16;
    const int KC8 = KC >> 3;
    const int chunksA = 128 * KC8;
    const int chunksB = KC * 16;

    for (int c0 = 0; c0 < K; c0 += KC) {
        for (int q = tid; q < 2 * chunksA; q += 256) {
            int hi = q < chunksA;
            int qq = hi ? q : q - chunksA;
            int r = qq / KC8, c = qq - r * KC8;
            uint4 val = make_uint4(0, 0, 0, 0);
            int gr = row0 + r;
            if (gr < NN) val = *(const uint4*)(Ain + (size_t)gr * (2 * K) + (hi ? 0 : K) + c0 + c * 8);
            *(uint4*)((hi ? A1 : A2) + r * APAD + c * 8) = val;
        }
        for (int q = tid; q < chunksB; q += 256) {
            int k = q >> 4, c = q & 15;
            uint4 val = *(const uint4*)(Wh + (size_t)(c0 + k) * 128 + c * 8);
            *(uint4*)(B1 + k * BPAD + c * 8) = val;
        }
        __syncthreads();

        uint32_t a1base = smem_u32(A1 + (rw + (lane & 15)) * APAD + ((lane >> 4) << 3));
        uint32_t a2base = smem_u32(A2 + (rw + (lane & 15)) * APAD + ((lane >> 4) << 3));
        uint32_t b1base = smem_u32(B1 + (lane & 15) * BPAD + ((lane >> 4) << 3));

        #pragma unroll 1
        for (int k0 = 0; k0 < KC; k0 += 16) {
            uint32_t p0, p1, p2, p3, q0, q1, q2, q3;
            asm volatile("ldmatrix.sync.aligned.m8n8.x4.shared.b16 {%0,%1,%2,%3}, [%4];"
                         : "=r"(p0), "=r"(p1), "=r"(p2), "=r"(p3) : "r"(a1base + (uint32_t)k0 * 2));
            asm volatile("ldmatrix.sync.aligned.m8n8.x4.shared.b16 {%0,%1,%2,%3}, [%4];"
                         : "=r"(q0), "=r"(q1), "=r"(q2), "=r"(q3) : "r"(a2base + (uint32_t)k0 * 2));
            uint32_t brow = b1base + (uint32_t)(k0 * BPAD) * 2;
            #pragma unroll
            for (int n2 = 0; n2 < 8; n2++) {
                uint32_t b0, b1, b2, b3;
                asm volatile("ldmatrix.sync.aligned.m8n8.x4.trans.shared.b16 {%0,%1,%2,%3}, [%4];"
                             : "=r"(b0), "=r"(b1), "=r"(b2), "=r"(b3)
                             : "r"(brow + (uint32_t)(n2 * 16) * 2));
                asm volatile("mma.sync.aligned.m16n8k16.row.col.f32.f16.f16.f32 "
                             "{%0,%1,%2,%3}, {%4,%5,%6,%7}, {%8,%9}, {%0,%1,%2,%3};"
                             : "+f"(acc[2*n2][0]), "+f"(acc[2*n2][1]), "+f"(acc[2*n2][2]), "+f"(acc[2*n2][3])
                             : "r"(p0), "r"(p1), "r"(p2), "r"(p3), "r"(b0), "r"(b1));
                asm volatile("mma.sync.aligned.m16n8k16.row.col.f32.f16.f16.f32 "
                             "{%0,%1,%2,%3}, {%4,%5,%6,%7}, {%8,%9}, {%0,%1,%2,%3};"
                             : "+f"(acc[2*n2+1][0]), "+f"(acc[2*n2+1][1]), "+f"(acc[2*n2+1][2]), "+f"(acc[2*n2+1][3])
                             : "r"(p0), "r"(p1), "r"(p2), "r"(p3), "r"(b2), "r"(b3));
                asm volatile("mma.sync.aligned.m16n8k16.row.col.f32.f16.f16.f32 "
                             "{%0,%1,%2,%3}, {%4,%5,%6,%7}, {%8,%9}, {%0,%1,%2,%3};"
                             : "+f"(acc[2*n2][0]), "+f"(acc[2*n2][1]), "+f"(acc[2*n2][2]), "+f"(acc[2*n2][3])
                             : "r"(q0), "r"(q1), "r"(q2), "r"(q3), "r"(b0), "r"(b1));
                asm volatile("mma.sync.aligned.m16n8k16.row.col.f32.f16.f16.f32 "
                             "{%0,%1,%2,%3}, {%4,%5,%6,%7}, {%8,%9}, {%0,%1,%2,%3};"
                             : "+f"(acc[2*n2+1][0]), "+f"(acc[2*n2+1][1]), "+f"(acc[2*n2+1][2]), "+f"(acc[2*n2+1][3])
                             : "r"(q0), "r"(q1), "r"(q2), "r"(q3), "r"(b2), "r"(b3));
            }
        }
        __syncthreads();
    }

    // epilogue: fp16 g_ht + fused a_s/a_d dots + global as max
    int qrow = lane >> 2;
    int qcol = (lane & 3) * 2;
    int r0 = rw + qrow, r1 = r0 + 8;
    int gr0 = row0 + r0, gr1 = row0 + r1;
    float as0 = 0.f, ad0 = 0.f, as1 = 0.f, ad1 = 0.f;
    #pragma unroll
    for (int n = 0; n < 16; n++) {
        int c = n * 8 + qcol;
        float w0 = s_as[c], w1 = s_as[c + 1];
        float u0 = s_ad[c], u1 = s_ad[c + 1];
        as0 += acc[n][0] * w0 + acc[n][1] * w1;
        ad0 += acc[n][0] * u0 + acc[n][1] * u1;
        as1 += acc[n][2] * w0 + acc[n][3] * w1;
        ad1 += acc[n][2] * u0 + acc[n][3] * u1;
    }
    if (gr0 < NN) {
        __half* d0 = g_ht + (size_t)gr0 * HIDV;
        #pragma unroll
        for (int n = 0; n < 16; n++)
            *(__half2*)(d0 + n * 8 + qcol) = __floats2half2_rn(acc[n][0], acc[n][1]);
    }
    if (gr1 < NN) {
        __half* d1 = g_ht + (size_t)gr1 * HIDV;
        #pragma unroll
        for (int n = 0; n < 16; n++)
            *(__half2*)(d1 + n * 8 + qcol) = __floats2half2_rn(acc[n][2], acc[n][3]);
    }
    #pragma unroll
    for (int o = 1; o < 4; o <<= 1) {
        as0 += __shfl_xor_sync(0xffffffffu, as0, o);
        ad0 += __shfl_xor_sync(0xffffffffu, ad0, o);
        as1 += __shfl_xor_sync(0xffffffffu, as1, o);
        ad1 += __shfl_xor_sync(0xffffffffu, ad1, o);
    }
    float mv = -3.4e38f;
    if ((lane & 3) == 0) {
        if (gr0 < NN) { g_as[gr0] = as0; g_ad[gr0] = ad0; mv = fmaxf(mv, as0); }
        if (gr1 < NN) { g_as[gr1] = as1; g_ad[gr1] = ad1; mv = fmaxf(mv, as1); }
    }
    #pragma unroll
    for (int o = 16; o > 0; o >>= 1) mv = fmaxf(mv, __shfl_xor_sync(0xffffffffu, mv, o));
    if (lane == 0 && mv > -3.0e38f) atomicMax(&g_asmax[widx], encf(mv));
}

// ---------------- aggregation: single-pass softmax, fp16 gather, MLP 8 ----
__global__ __launch_bounds__(256) void k_agg(const float* __restrict__ bias,
                                             int layer, int mode) {
    __shared__ uint2 pairs[8][32];
    int w = (blockIdx.x * blockDim.x + threadIdx.x) >> 5;
    if (w >= NN) return;
    int lane = threadIdx.x & 31;
    int wl = (threadIdx.x >> 5) & 7;

    float ad = g_ad[w];
    float m = lrelu02(decf(g_asmax[layer]) + ad);
    float wself = __expf(lrelu02(g_as[w] + ad) - m);
    uint2 hv0 = *(const uint2*)(g_ht + (size_t)w * HIDV + lane * 4);
    float2 hl = __half22float2(*(__half2*)&hv0.x);
    float2 hh = __half22float2(*(__half2*)&hv0.y);
    float4 acc = make_float4(wself * hl.x, wself * hl.y, wself * hh.x, wself * hh.y);
    float se = 0.f;

    int beg = g_rowptr[w], cnt = g_deg[w];
    for (int base = 0; base < cnt; base += 32) {
        int i = base + lane;
        int srci = 0;
        float wgt = 0.f;
        if (i < cnt) {
            srci = g_col[beg + i];
            wgt = __expf(lrelu02(g_as[srci] + ad) - m);
            se += wgt;
        }
        __syncwarp();
        pairs[wl][lane] = make_uint2((unsigned)srci, __float_as_uint(wgt));
        __syncwarp();
        int lim = min(32, cnt - base);
        int j = 0;
        for (; j + 8 <= lim; j += 8) {
            uint2 p0 = pairs[wl][j],     p1 = pairs[wl][j + 1];
            uint2 p2 = pairs[wl][j + 2], p3 = pairs[wl][j + 3];
            uint2 p4 = pairs[wl][j + 4], p5 = pairs[wl][j + 5];
            uint2 p6 = pairs[wl][j + 6], p7 = pairs[wl][j + 7];
            uint2 r0 = *(const uint2*)(g_ht + (size_t)p0.x * HIDV + lane * 4);
            uint2 r1 = *(const uint2*)(g_ht + (size_t)p1.x * HIDV + lane * 4);
            uint2 r2 = *(const uint2*)(g_ht + (size_t)p2.x * HIDV + lane * 4);
            uint2 r3 = *(const uint2*)(g_ht + (size_t)p3.x * HIDV + lane * 4);
            uint2 r4 = *(const uint2*)(g_ht + (size_t)p4.x * HIDV + lane * 4);
            uint2 r5 = *(const uint2*)(g_ht + (size_t)p5.x * HIDV + lane * 4);
            uint2 r6 = *(const uint2*)(g_ht + (size_t)p6.x * HIDV + lane * 4);
            uint2 r7 = *(const uint2*)(g_ht + (size_t)p7.x * HIDV + lane * 4);
            float w0 = __uint_as_float(p0.y), w1 = __uint_as_float(p1.y);
            float w2 = __uint_as_float(p2.y), w3 = __uint_as_float(p3.y);
            float w4 = __uint_as_float(p4.y), w5 = __uint_as_float(p5.y);
            float w6 = __uint_as_float(p6.y), w7 = __uint_as_float(p7.y);
            float2 a0 = __half22float2(*(__half2*)&r0.x), b0 = __half22float2(*(__half2*)&r0.y);
            float2 a1 = __half22float2(*(__half2*)&r1.x), b1 = __half22float2(*(__half2*)&r1.y);
            float2 a2 = __half22float2(*(__half2*)&r2.x), b2 = __half22float2(*(__half2*)&r2.y);
            float2 a3 = __half22float2(*(__half2*)&r3.x), b3 = __half22float2(*(__half2*)&r3.y);
            float2 a4 = __half22float2(*(__half2*)&r4.x), b4 = __half22float2(*(__half2*)&r4.y);
            float2 a5 = __half22float2(*(__half2*)&r5.x), b5 = __half22float2(*(__half2*)&r5.y);
            float2 a6 = __half22float2(*(__half2*)&r6.x), b6 = __half22float2(*(__half2*)&r6.y);
            float2 a7 = __half22float2(*(__half2*)&r7.x), b7 = __half22float2(*(__half2*)&r7.y);
            acc.x += w0 * a0.x + w1 * a1.x + w2 * a2.x + w3 * a3.x
                   + w4 * a4.x + w5 * a5.x + w6 * a6.x + w7 * a7.x;
            acc.y += w0 * a0.y + w1 * a1.y + w2 * a2.y + w3 * a3.y
                   + w4 * a4.y + w5 * a5.y + w6 * a6.y + w7 * a7.y;
            acc.z += w0 * b0.x + w1 * b1.x + w2 * b2.x + w3 * b3.x
                   + w4 * b4.x + w5 * b5.x + w6 * b6.x + w7 * b7.x;
            acc.w += w0 * b0.y + w1 * b1.y + w2 * b2.y + w3 * b3.y
                   + w4 * b4.y + w5 * b5.y + w6 * b6.y + w7 * b7.y;
        }
        for (; j < lim; j++) {
            uint2 p = pairs[wl][j];
            float wj = __uint_as_float(p.y);
            uint2 rv = *(const uint2*)(g_ht + (size_t)p.x * HIDV + lane * 4);
            float2 aa = __half22float2(*(__half2*)&rv.x), bb2 = __half22float2(*(__half2*)&rv.y);
            acc.x += wj * aa.x; acc.y += wj * aa.y;
            acc.z += wj * bb2.x; acc.w += wj * bb2.y;
        }
    }
    #pragma unroll
    for (int o = 16; o > 0; o >>= 1) se += __shfl_xor_sync(0xffffffffu, se, o);
    float inv = 1.0f / (wself + se);
    float4 bb = *(const float4*)(bias + lane * 4);
    float4 o;
    o.x = gelu_tanh(acc.x * inv + bb.x);
    o.y = gelu_tanh(acc.y * inv + bb.y);
    o.z = gelu_tanh(acc.z * inv + bb.z);
    o.w = gelu_tanh(acc.w * inv + bb.w);
    if (mode == 0) {
        // split to fp16 hi/lo for next layer's GEMM
        __half h0 = __float2half_rn(o.x), h1 = __float2half_rn(o.y);
        __half h2 = __float2half_rn(o.z), h3 = __float2half_rn(o.w);
        __half l0 = __float2half_rn(o.x - __half2float(h0));
        __half l1 = __float2half_rn(o.y - __half2float(h1));
        __half l2 = __float2half_rn(o.z - __half2float(h2));
        __half l3 = __float2half_rn(o.w - __half2float(h3));
        __half* row = g_hs + (size_t)w * (2 * HIDV);
        __half2 hv01 = __halves2half2(h0, h1), hv23 = __halves2half2(h2, h3);
        __half2 lv01 = __halves2half2(l0, l1), lv23 = __halves2half2(l2, l3);
        uint2 hv = make_uint2(*(uint32_t*)&hv01, *(uint32_t*)&hv23);
        uint2 lv = make_uint2(*(uint32_t*)&lv01, *(uint32_t*)&lv23);
        *(uint2*)(row + lane * 4) = hv;
        *(uint2*)(row + HIDV + lane * 4) = lv;
    } else {
        *(float4*)(g_hA + (size_t)w * HIDV + lane * 4) = o;
    }
}

// ---------------- global add pool: 1024 blocks ----------------
__global__ void k_pool(const int* __restrict__ batch) {
    const float* h = g_hA;
    int c = threadIdx.x;
    int per = (NN + gridDim.x - 1) / gridDim.x;
    int n0 = blockIdx.x * per;
    int n1 = n0 + per;
    if (n1 > NN) n1 = NN;
    if (n0 >= n1) return;
    float acc = 0.f;
    int cg = batch[n0];
    #pragma unroll 4
    for (int n = n0; n < n1; n++) {
        int bg = batch[n];
        if (bg != cg) {
            atomicAdd(&g_pool[(size_t)cg * HIDV + c], acc);
            acc = 0.f;
            cg = bg;
        }
        acc += h[(size_t)n * HIDV + c];
    }
    atomicAdd(&g_pool[(size_t)cg * HIDV + c], acc);
}

// ---------------- final FC + leaky ----------------
__global__ void k_fc(const float* __restrict__ fcW, const float* __restrict__ fcb,
                     float* __restrict__ out) {
    int gi = blockIdx.x;
    int oc = threadIdx.x;
    float s = fcb[oc];
    #pragma unroll 8
    for (int k = 0; k < HIDV; k++)
        s += g_pool[(size_t)gi * HIDV + k] * fcW[(size_t)k * OUT_DIMV + oc];
    s = s > 0.f ? s : 0.01f * s;
    out[(size_t)gi * OUT_DIMV + oc] = s;
}

// ---------------- launcher ----------------
extern "C" void kernel_launch(void* const* d_in, const int* in_sizes, int n_in,
                              void* d_out, int out_size) {
    const float* x       = (const float*)d_in[0];
    const int*   nodeidx = (const int*)  d_in[1];
    const int*   eidx    = (const int*)  d_in[2];
    const int*   batch   = (const int*)  d_in[3];
    const float* emb     = (const float*)d_in[4];
    const float* W1      = (const float*)d_in[5];
    const float* a1s     = (const float*)d_in[6];
    const float* a1d     = (const float*)d_in[7];
    const float* b1      = (const float*)d_in[8];
    const float* W2      = (const float*)d_in[9];
    const float* a2s     = (const float*)d_in[10];
    const float* a2d     = (const float*)d_in[11];
    const float* b2      = (const float*)d_in[12];
    const float* W3      = (const float*)d_in[13];
    const float* a3s     = (const float*)d_in[14];
    const float* a3d     = (const float*)d_in[15];
    const float* b3      = (const float*)d_in[16];
    const float* fcW     = (const float*)d_in[17];
    const float* fcb     = (const float*)d_in[18];
    float* out = (float*)d_out;

    const int* src = eidx;
    const int* dst = eidx + EE;

    // K=192: KC=96, 2 chunks, smem ≈ (2*128*104 + 96*136)*2 + 1024 ≈ 79 KB (2 CTAs/SM)
    // K=128: KC=128, 1 chunk, smem ≈ (2*128*136 + 128*136)*2 + 1024 ≈ 104 KB (2 CTAs/SM)
    const int smem1 = (2 * 128 * (96 + 8) + 96 * 136) * 2 + 1024;
    const int smem2 = (2 * 128 * (128 + 8) + 128 * 136) * 2 + 1024;
    cudaFuncSetAttribute(k_mma, cudaFuncAttributeMaxDynamicSharedMemorySize,
                         smem1 > smem2 ? smem1 : smem2);

    const int mma_blocks = (NN + 127) / 128;
    const int agg_blocks = (NN * 32 + 255) / 256;

    k_init<<<242, 512>>>(W1, W2, W3);                                  // 0
    k_h0<<<NN, 128>>>(x, nodeidx, emb, dst);                           // 1 (+hist)
    k_scan<<<49, 1024>>>();                                            // 2
    k_mma<<<mma_blocks, 256, smem1>>>(0, CIN1, 96, 0, a1s, a1d);       // 3  <- ncu slot
    k_scatter<<<1600, 512>>>(src, dst);                                // 4
    k_agg<<<agg_blocks, 256>>>(b1, 0, 0);                              // 5
    k_mma<<<mma_blocks, 256, smem2>>>(1, HIDV, 128, 1, a2s, a2d);      // 6
    k_agg<<<agg_blocks, 256>>>(b2, 1, 0);                              // 7
    k_mma<<<mma_blocks, 256, smem2>>>(1, HIDV, 128, 2, a3s, a3d);      // 8
    k_agg<<<agg_blocks, 256>>>(b3, 2, 1);                              // 9
    k_pool<<<1024, HIDV>>>(batch);                                     // 10
    k_fc<<<NGRAPH, OUT_DIMV>>>(fcW, fcb, out);                         // 11
}